// round 2
// baseline (speedup 1.0000x reference)
#include <cuda_runtime.h>
#include <cuda_bf16.h>
#include <math.h>

#define BB 16
#define NN 512
#define DD 256
#define HH 8
#define DK 32
#define LL 4
#define BN (BB * NN)   // 8192

// ---------------- scratch (static device globals; no runtime alloc) ----------------
__device__ float g_x[BN * DD];
__device__ float g_h[BN * DD];
__device__ float g_q[BN * DD];
__device__ float g_k[BN * DD];
__device__ float g_v[BN * DD];
__device__ float g_att[BN * DD];
__device__ float g_h2[BN * DD];
__device__ float g_M[BB * NN * NN];   // 0.3*p_dist + 0.4*p_adj (layer-independent)

// ---------------- simple copy ----------------
__global__ void copy_kernel(float* __restrict__ dst, const float* __restrict__ src, int n) {
    int i = blockIdx.x * blockDim.x + threadIdx.x;
    if (i < n) dst[i] = src[i];
}

// ---------------- precompute M = 0.3*softmax(masked -dist) + 0.4*adj/rowsum ----------------
__global__ void precompute_M_kernel(const float* __restrict__ adj,
                                    const float* __restrict__ dist,
                                    const int* __restrict__ mask,
                                    float* __restrict__ Mout) {
    int i = blockIdx.x;      // row (query) index
    int b = blockIdx.y;      // batch
    int tid = threadIdx.x;   // 256
    const float* arow = adj  + ((long)b * NN + i) * NN;
    const float* drow = dist + ((long)b * NN + i) * NN;
    const int*   mrow = mask + (long)b * NN;
    __shared__ float sh[256];

    // adj row sum (unmasked, per reference)
    float asum = 0.f;
    for (int j = tid; j < NN; j += 256) asum += arow[j];
    sh[tid] = asum; __syncthreads();
    for (int s = 128; s > 0; s >>= 1) { if (tid < s) sh[tid] += sh[tid + s]; __syncthreads(); }
    asum = sh[0]; __syncthreads();

    // masked max of -dist
    float dmax = -INFINITY;
    for (int j = tid; j < NN; j += 256) if (mrow[j]) dmax = fmaxf(dmax, -drow[j]);
    sh[tid] = dmax; __syncthreads();
    for (int s = 128; s > 0; s >>= 1) { if (tid < s) sh[tid] = fmaxf(sh[tid], sh[tid + s]); __syncthreads(); }
    dmax = sh[0]; __syncthreads();

    // masked exp-sum
    float esum = 0.f;
    for (int j = tid; j < NN; j += 256) if (mrow[j]) esum += __expf(-drow[j] - dmax);
    sh[tid] = esum; __syncthreads();
    for (int s = 128; s > 0; s >>= 1) { if (tid < s) sh[tid] += sh[tid + s]; __syncthreads(); }
    esum = sh[0]; __syncthreads();

    float inv_d = 0.3f / esum;
    float inv_a = 0.4f / (asum + 1e-6f);
    float* orow = Mout + ((long)b * NN + i) * NN;
    for (int j = tid; j < NN; j += 256) {
        float pd = mrow[j] ? __expf(-drow[j] - dmax) * inv_d : 0.f;
        orow[j] = pd + arow[j] * inv_a;
    }
}

// ---------------- layernorm (ddof=1, divide by (std+eps)) ----------------
__global__ void layernorm_kernel(const float* __restrict__ in, float* __restrict__ out,
                                 const float* __restrict__ ga, const float* __restrict__ gb) {
    __shared__ float sh[256];
    long row = blockIdx.x;
    int tid = threadIdx.x;
    float v = in[row * DD + tid];
    sh[tid] = v; __syncthreads();
    for (int s = 128; s > 0; s >>= 1) { if (tid < s) sh[tid] += sh[tid + s]; __syncthreads(); }
    float mean = sh[0] * (1.0f / (float)DD);
    __syncthreads();
    float d = v - mean;
    sh[tid] = d * d; __syncthreads();
    for (int s = 128; s > 0; s >>= 1) { if (tid < s) sh[tid] += sh[tid + s]; __syncthreads(); }
    float sd = sqrtf(sh[0] / (float)(DD - 1));
    out[row * DD + tid] = ga[tid] * d / (sd + 1e-6f) + gb[tid];
}

// ---------------- tiled GEMM with fused epilogues ----------------
// C[M x Nc] = A[M x K] @ W[K x Nc]  (+ bias / residual / leaky-relu / accumulate)
// epi: 0 = +bias ; 1 = +bias +res ; 2 = lrelu(+bias) ; 3 = lrelu(+bias)+res ; 4 = C += acc
#define TM 64
#define TN 64
#define TK 16
__global__ void gemm_kernel(const float* __restrict__ A, const float* __restrict__ W,
                            const float* __restrict__ bias, const float* __restrict__ res,
                            float* __restrict__ C, int M, int Nc, int K,
                            long bsA, long bsB, long bsC, int epi) {
    __shared__ float As[TK][TM + 1];
    __shared__ float Bs[TK][TN];
    int bz = blockIdx.z;
    A += (long)bz * bsA;
    W += (long)bz * bsB;
    C += (long)bz * bsC;
    if (res) res += (long)bz * bsC;

    int m0 = blockIdx.y * TM;
    int n0 = blockIdx.x * TN;
    int tid = threadIdx.x;           // 256
    int tx = tid & 15, ty = tid >> 4;

    int la_c = tid & 15;             // A tile: 64 rows x 16 cols
    int la_r = tid >> 4;
    int lb_c = tid & 63;             // B tile: 16 rows x 64 cols
    int lb_r = tid >> 6;

    float acc[4][4] = {};
    for (int k0 = 0; k0 < K; k0 += TK) {
        #pragma unroll
        for (int it = 0; it < 4; it++) {
            int r = la_r + it * 16;
            As[la_c][r] = A[(long)(m0 + r) * K + k0 + la_c];
        }
        #pragma unroll
        for (int it = 0; it < 4; it++) {
            int r = lb_r + it * 4;
            Bs[r][lb_c] = W[(long)(k0 + r) * Nc + n0 + lb_c];
        }
        __syncthreads();
        #pragma unroll
        for (int kk = 0; kk < TK; kk++) {
            float a[4], b[4];
            #pragma unroll
            for (int i = 0; i < 4; i++) a[i] = As[kk][ty * 4 + i];
            #pragma unroll
            for (int j = 0; j < 4; j++) b[j] = Bs[kk][tx * 4 + j];
            #pragma unroll
            for (int i = 0; i < 4; i++)
                #pragma unroll
                for (int j = 0; j < 4; j++)
                    acc[i][j] += a[i] * b[j];
        }
        __syncthreads();
    }
    #pragma unroll
    for (int i = 0; i < 4; i++) {
        int m = m0 + ty * 4 + i;
        #pragma unroll
        for (int j = 0; j < 4; j++) {
            int n = n0 + tx * 4 + j;
            long idx = (long)m * Nc + n;
            float v = acc[i][j];
            if (epi == 0)      { v += bias[n]; }
            else if (epi == 1) { v += bias[n] + res[idx]; }
            else if (epi == 2) { v += bias[n]; v = (v > 0.f) ? v : 0.1f * v; }
            else if (epi == 3) { v += bias[n]; v = (v > 0.f) ? v : 0.1f * v; v += res[idx]; }
            else               { v += C[idx]; }
            C[idx] = v;
        }
    }
}

// ---------------- flash attention: Og = 0.3 * softmax_masked(Q K^T / sqrt(dk)) @ V ----------------
// grid: (N/64, H, B); block: 256 threads; thread = (row 0..63, c 0..3)
#define FQ 64
#define FK 64
__global__ void flash_kernel(const float* __restrict__ Qg, const float* __restrict__ Kg,
                             const float* __restrict__ Vg, const int* __restrict__ mask,
                             float* __restrict__ Og) {
    int qt = blockIdx.x, h = blockIdx.y, b = blockIdx.z;
    int tid = threadIdx.x;
    int row = tid >> 2;   // 0..63
    int c   = tid & 3;    // 0..3
    __shared__ float Qs[FQ][DK];
    __shared__ float Ks[FK][DK];
    __shared__ float Vs[FK][DK];

    const float scale = 0.1767766952966369f;  // 1/sqrt(32)
    long qbase = ((long)(b * NN) + qt * FQ) * DD + h * DK;
    for (int idx = tid; idx < FQ * DK; idx += 256) {
        int r = idx >> 5, d = idx & 31;
        Qs[r][d] = Qg[qbase + (long)r * DD + d] * scale;
    }
    __syncthreads();
    float qreg[DK];
    #pragma unroll
    for (int d = 0; d < DK; d++) qreg[d] = Qs[row][d];

    float m = -INFINITY, l = 0.f;
    float O[DK];
    #pragma unroll
    for (int d = 0; d < DK; d++) O[d] = 0.f;

    for (int kt = 0; kt < NN; kt += FK) {
        __syncthreads();
        long kbase = ((long)(b * NN) + kt) * DD + h * DK;
        for (int idx = tid; idx < FK * DK; idx += 256) {
            int r = idx >> 5, d = idx & 31;
            Ks[r][d] = Kg[kbase + (long)r * DD + d];
            Vs[r][d] = Vg[kbase + (long)r * DD + d];
        }
        __syncthreads();

        float s[16];
        float tmax = -INFINITY;
        #pragma unroll
        for (int jj = 0; jj < 16; jj++) {
            int j = c * 16 + jj;
            float sv = 0.f;
            #pragma unroll
            for (int d = 0; d < DK; d++) sv += qreg[d] * Ks[j][d];
            sv = mask[b * NN + kt + j] ? sv : -1e12f;
            s[jj] = sv;
            tmax = fmaxf(tmax, sv);
        }
        tmax = fmaxf(tmax, __shfl_xor_sync(0xffffffffu, tmax, 1));
        tmax = fmaxf(tmax, __shfl_xor_sync(0xffffffffu, tmax, 2));
        float mnew = fmaxf(m, tmax);
        float alpha = __expf(m - mnew);
        float p[16];
        float lsum = 0.f;
        #pragma unroll
        for (int jj = 0; jj < 16; jj++) { p[jj] = __expf(s[jj] - mnew); lsum += p[jj]; }
        lsum += __shfl_xor_sync(0xffffffffu, lsum, 1);
        lsum += __shfl_xor_sync(0xffffffffu, lsum, 2);
        l = l * alpha + lsum;
        m = mnew;
        #pragma unroll
        for (int d = 0; d < DK; d++) O[d] *= alpha;
        #pragma unroll
        for (int jj = 0; jj < 16; jj++) {
            int j = c * 16 + jj;
            float pv = p[jj];
            #pragma unroll
            for (int d = 0; d < DK; d++) O[d] += pv * Vs[j][d];
        }
    }
    // combine the 4 partial accumulators per row
    #pragma unroll
    for (int d = 0; d < DK; d++) {
        O[d] += __shfl_xor_sync(0xffffffffu, O[d], 1);
        O[d] += __shfl_xor_sync(0xffffffffu, O[d], 2);
    }
    float inv = 0.3f / l;
    long obase = ((long)(b * NN) + qt * FQ + row) * DD + h * DK;
    #pragma unroll
    for (int dd = 0; dd < 8; dd++) {
        int d = c * 8 + dd;
        Og[obase + d] = O[d] * inv;
    }
}

// ---------------- host launch ----------------
extern "C" void kernel_launch(void* const* d_in, const int* in_sizes, int n_in,
                              void* d_out, int out_size) {
    const float* x      = (const float*)d_in[0];
    const int*   mask   = (const int*)d_in[1];
    const float* adj    = (const float*)d_in[2];
    const float* dist   = (const float*)d_in[3];
    // d_in[4] = edges_att (unused)
    const float* Wq  = (const float*)d_in[5];
    const float* bq  = (const float*)d_in[6];
    const float* Wk  = (const float*)d_in[7];
    const float* bk  = (const float*)d_in[8];
    const float* Wv  = (const float*)d_in[9];
    const float* bv  = (const float*)d_in[10];
    const float* Wo  = (const float*)d_in[11];
    const float* bo  = (const float*)d_in[12];
    const float* Wf1 = (const float*)d_in[13];
    const float* bf1 = (const float*)d_in[14];
    const float* Wf2 = (const float*)d_in[15];
    const float* bf2 = (const float*)d_in[16];
    const float* ln1a = (const float*)d_in[17];
    const float* ln1b = (const float*)d_in[18];
    const float* ln2a = (const float*)d_in[19];
    const float* ln2b = (const float*)d_in[20];
    const float* lnfa = (const float*)d_in[21];
    const float* lnfb = (const float*)d_in[22];

    float *px, *ph, *pq, *pk, *pv, *patt, *ph2, *pM;
    cudaGetSymbolAddress((void**)&px,   g_x);
    cudaGetSymbolAddress((void**)&ph,   g_h);
    cudaGetSymbolAddress((void**)&pq,   g_q);
    cudaGetSymbolAddress((void**)&pk,   g_k);
    cudaGetSymbolAddress((void**)&pv,   g_v);
    cudaGetSymbolAddress((void**)&patt, g_att);
    cudaGetSymbolAddress((void**)&ph2,  g_h2);
    cudaGetSymbolAddress((void**)&pM,   g_M);

    const int nElem = BN * DD;
    copy_kernel<<<(nElem + 255) / 256, 256>>>(px, x, nElem);
    precompute_M_kernel<<<dim3(NN, BB), 256>>>(adj, dist, mask, pM);

    dim3 gemm_grid(DD / TN, BN / TM, 1);          // 4 x 128
    dim3 gemm_grid_b(DD / TN, NN / TM, BB);       // 4 x 8 x 16 (batched M@V)

    for (int i = 0; i < LL; i++) {
        const float* wq = Wq + (long)i * DD * DD;
        const float* wk = Wk + (long)i * DD * DD;
        const float* wv = Wv + (long)i * DD * DD;
        const float* wo = Wo + (long)i * DD * DD;
        const float* w1 = Wf1 + (long)i * DD * DD;
        const float* w2 = Wf2 + (long)i * DD * DD;

        layernorm_kernel<<<BN, 256>>>(px, ph, ln1a + i * DD, ln1b + i * DD);

        gemm_kernel<<<gemm_grid, 256>>>(ph, wq, bq + i * DD, nullptr, pq, BN, DD, DD, 0, 0, 0, 0);
        gemm_kernel<<<gemm_grid, 256>>>(ph, wk, bk + i * DD, nullptr, pk, BN, DD, DD, 0, 0, 0, 0);
        gemm_kernel<<<gemm_grid, 256>>>(ph, wv, bv + i * DD, nullptr, pv, BN, DD, DD, 0, 0, 0, 0);

        flash_kernel<<<dim3(NN / FQ, HH, BB), 256>>>(pq, pk, pv, mask, patt);

        // att += M @ V   (blend of dist/adj paths, all heads at once)
        gemm_kernel<<<gemm_grid_b, 256>>>(pM, pv, nullptr, nullptr, patt, NN, DD, NN,
                                          (long)NN * NN, (long)NN * DD, (long)NN * DD, 4);

        // x = x + att @ Wo + bo
        gemm_kernel<<<gemm_grid, 256>>>(patt, wo, bo + i * DD, px, px, BN, DD, DD, 0, 0, 0, 1);

        layernorm_kernel<<<BN, 256>>>(px, ph, ln2a + i * DD, ln2b + i * DD);
        gemm_kernel<<<gemm_grid, 256>>>(ph, w1, bf1 + i * DD, nullptr, ph2, BN, DD, DD, 0, 0, 0, 2);
        gemm_kernel<<<gemm_grid, 256>>>(ph2, w2, bf2 + i * DD, px, px, BN, DD, DD, 0, 0, 0, 3);
    }

    layernorm_kernel<<<BN, 256>>>(px, (float*)d_out, lnfa, lnfb);
}

// round 5
// speedup vs baseline: 2.6462x; 2.6462x over previous
#include <cuda_runtime.h>
#include <cuda_bf16.h>
#include <math.h>

#define BB 16
#define NN 512
#define DD 256
#define HH 8
#define DK 32
#define LL 4
#define ROWS_TOTAL (BB * NN)   // 8192

// ---------------- scratch (static device globals; no runtime alloc) ----------------
__device__ float g_x[ROWS_TOTAL * DD];
__device__ float g_h[ROWS_TOTAL * DD];
__device__ float g_qkv[ROWS_TOTAL * 3 * DD];       // fused Q|K|V, row stride 768
__device__ float g_att[ROWS_TOTAL * DD];
__device__ float g_h2[ROWS_TOTAL * DD];
__device__ float g_M[BB * NN * NN];                // 0.3*p_dist + 0.4*p_adj (layer-independent)
__device__ float g_S[(long)BB * HH * NN * NN];     // scores / blended probs (in-place), 134MB
__device__ float g_Wqkv[LL * DD * 3 * DD];         // packed [L][256][768]
__device__ float g_bqkv[LL * 3 * DD];

// ---------------- copy (float4) ----------------
__global__ void copy_kernel(float4* __restrict__ dst, const float4* __restrict__ src, int n4) {
    int i = blockIdx.x * blockDim.x + threadIdx.x;
    if (i < n4) dst[i] = src[i];
}

// ---------------- pack Wq|Wk|Wv -> [L][256][768], biases -> [L][768] ----------------
__global__ void pack_qkv_kernel(const float* __restrict__ Wq, const float* __restrict__ Wk,
                                const float* __restrict__ Wv, const float* __restrict__ bq,
                                const float* __restrict__ bk, const float* __restrict__ bv,
                                float* __restrict__ W, float* __restrict__ bias) {
    long idx = (long)blockIdx.x * 256 + threadIdx.x;   // L*256*768 = 786432
    long l = idx / (DD * 3 * DD);
    int rem = (int)(idx % (DD * 3 * DD));
    int k = rem / (3 * DD), j = rem % (3 * DD);
    int which = j >> 8, jj = j & 255;
    const float* src = which == 0 ? Wq : (which == 1 ? Wk : Wv);
    W[idx] = src[(l * DD + k) * DD + jj];
    if (idx < LL * 3 * DD) {
        long l2 = idx / (3 * DD);
        int j2 = (int)(idx % (3 * DD));
        int w2 = j2 >> 8, jj2 = j2 & 255;
        const float* bs = w2 == 0 ? bq : (w2 == 1 ? bk : bv);
        bias[idx] = bs[l2 * DD + jj2];
    }
}

// ---------------- precompute M = 0.3*softmax(masked -dist) + 0.4*adj/rowsum ----------------
__global__ void precompute_M_kernel(const float* __restrict__ adj,
                                    const float* __restrict__ dist,
                                    const int* __restrict__ mask,
                                    float* __restrict__ Mout) {
    int i = blockIdx.x;
    int b = blockIdx.y;
    int tid = threadIdx.x;   // 256
    const float* arow = adj  + ((long)b * NN + i) * NN;
    const float* drow = dist + ((long)b * NN + i) * NN;
    const int*   mrow = mask + (long)b * NN;
    __shared__ float sh[256];

    float asum = 0.f;
    for (int j = tid; j < NN; j += 256) asum += arow[j];
    sh[tid] = asum; __syncthreads();
    for (int s = 128; s > 0; s >>= 1) { if (tid < s) sh[tid] += sh[tid + s]; __syncthreads(); }
    asum = sh[0]; __syncthreads();

    float dmax = -INFINITY;
    for (int j = tid; j < NN; j += 256) if (mrow[j]) dmax = fmaxf(dmax, -drow[j]);
    sh[tid] = dmax; __syncthreads();
    for (int s = 128; s > 0; s >>= 1) { if (tid < s) sh[tid] = fmaxf(sh[tid], sh[tid + s]); __syncthreads(); }
    dmax = sh[0]; __syncthreads();

    float esum = 0.f;
    for (int j = tid; j < NN; j += 256) if (mrow[j]) esum += __expf(-drow[j] - dmax);
    sh[tid] = esum; __syncthreads();
    for (int s = 128; s > 0; s >>= 1) { if (tid < s) sh[tid] += sh[tid + s]; __syncthreads(); }
    esum = sh[0]; __syncthreads();

    float inv_d = 0.3f / esum;
    float inv_a = 0.4f / (asum + 1e-6f);
    float* orow = Mout + ((long)b * NN + i) * NN;
    for (int j = tid; j < NN; j += 256) {
        float pd = mrow[j] ? __expf(-drow[j] - dmax) * inv_d : 0.f;
        orow[j] = pd + arow[j] * inv_a;
    }
}

// ---------------- layernorm (ddof=1, divide by (std+eps)), single pass ----------------
__global__ void layernorm_kernel(const float* __restrict__ in, float* __restrict__ out,
                                 const float* __restrict__ ga, const float* __restrict__ gb) {
    __shared__ float shs[8], shs2[8];
    long row = blockIdx.x;
    int tid = threadIdx.x;
    float v = in[row * DD + tid];
    float s = v, s2 = v * v;
    #pragma unroll
    for (int o = 16; o; o >>= 1) {
        s  += __shfl_xor_sync(0xffffffffu, s, o);
        s2 += __shfl_xor_sync(0xffffffffu, s2, o);
    }
    int w = tid >> 5, l = tid & 31;
    if (l == 0) { shs[w] = s; shs2[w] = s2; }
    __syncthreads();
    float ts = 0.f, ts2 = 0.f;
    #pragma unroll
    for (int k = 0; k < 8; k++) { ts += shs[k]; ts2 += shs2[k]; }
    float mean = ts * (1.0f / 256.0f);
    float var = fmaxf((ts2 - 256.0f * mean * mean) * (1.0f / 255.0f), 0.0f);
    float sd = sqrtf(var);
    out[row * DD + tid] = ga[tid] * (v - mean) / (sd + 1e-6f) + gb[tid];
}

// ---------------- templated tiled GEMM, 8-wide K-step, register micro-tiles ----------------
// epi bits: 1 = +bias[n]; 2 = leaky-relu(0.1); 4 = +res[idx]
// batching: z -> (zb = z/hdiv, zh = z%hdiv); offsets via per-matrix strides.
template<int GM, int GN, int TY, int TX, bool TRANSB>
__global__ __launch_bounds__(256, 2)
void gemm_t(const float* __restrict__ A, const float* __restrict__ B,
            const float* __restrict__ bias, const float* __restrict__ res,
            float* __restrict__ C,
            int K, int lda, int ldb, int ldc,
            int hdiv, long sAb, long sAh, long sBb, long sBh, long sCb, long sCh,
            int epi) {
    constexpr int RM = GM / TY;
    constexpr int RN = GN / TX;
    constexpr int TK = 8;
    __shared__ float As[TK][GM + 4];
    __shared__ float Bs[TK][GN + 4];

    int z = blockIdx.z;
    int zb = z / hdiv, zh = z % hdiv;
    A += zb * sAb + zh * sAh;
    B += zb * sBb + zh * sBh;
    C += zb * sCb + zh * sCh;
    if (res) res += zb * sCb + zh * sCh;

    int m0 = blockIdx.y * GM, n0 = blockIdx.x * GN;
    int tid = threadIdx.x;
    int tx = tid % TX, ty = tid / TX;

    float acc[RM][RN] = {};

    for (int k0 = 0; k0 < K; k0 += TK) {
        {
            constexpr int TOT = GM * TK / 4;
            #pragma unroll
            for (int ii = tid; ii < TOT; ii += 256) {
                int i = ii * 4;
                int r = i / TK, c = i % TK;
                const float4 av = *(const float4*)(A + (long)(m0 + r) * lda + k0 + c);
                As[c + 0][r] = av.x; As[c + 1][r] = av.y;
                As[c + 2][r] = av.z; As[c + 3][r] = av.w;
            }
        }
        if (!TRANSB) {
            constexpr int TOT = TK * GN / 4;
            #pragma unroll
            for (int ii = tid; ii < TOT; ii += 256) {
                int i = ii * 4;
                int r = i / GN, c = i % GN;
                *(float4*)&Bs[r][c] = *(const float4*)(B + (long)(k0 + r) * ldb + n0 + c);
            }
        } else {
            constexpr int TOT = GN * TK / 4;
            #pragma unroll
            for (int ii = tid; ii < TOT; ii += 256) {
                int i = ii * 4;
                int r = i / TK, c = i % TK;   // r = n index, c = k index
                const float4 bv = *(const float4*)(B + (long)(n0 + r) * ldb + k0 + c);
                Bs[c + 0][r] = bv.x; Bs[c + 1][r] = bv.y;
                Bs[c + 2][r] = bv.z; Bs[c + 3][r] = bv.w;
            }
        }
        __syncthreads();
        #pragma unroll
        for (int kk = 0; kk < TK; kk++) {
            float a[RM], b[RN];
            #pragma unroll
            for (int i = 0; i < RM / 4; i++)
                *(float4*)&a[i * 4] = *(const float4*)&As[kk][ty * RM + i * 4];
            #pragma unroll
            for (int j = 0; j < RN / 4; j++)
                *(float4*)&b[j * 4] = *(const float4*)&Bs[kk][tx * RN + j * 4];
            #pragma unroll
            for (int i = 0; i < RM; i++)
                #pragma unroll
                for (int j = 0; j < RN; j++)
                    acc[i][j] += a[i] * b[j];
        }
        __syncthreads();
    }

    #pragma unroll
    for (int i = 0; i < RM; i++) {
        int m = m0 + ty * RM + i;
        #pragma unroll
        for (int j4 = 0; j4 < RN; j4 += 4) {
            int n = n0 + tx * RN + j4;
            long idx = (long)m * ldc + n;
            float4 v = make_float4(acc[i][j4], acc[i][j4 + 1], acc[i][j4 + 2], acc[i][j4 + 3]);
            if (epi & 1) {
                float4 bb = *(const float4*)(bias + n);
                v.x += bb.x; v.y += bb.y; v.z += bb.z; v.w += bb.w;
            }
            if (epi & 2) {
                v.x = v.x > 0.f ? v.x : 0.1f * v.x;
                v.y = v.y > 0.f ? v.y : 0.1f * v.y;
                v.z = v.z > 0.f ? v.z : 0.1f * v.z;
                v.w = v.w > 0.f ? v.w : 0.1f * v.w;
            }
            if (epi & 4) {
                float4 rr = *(const float4*)(res + idx);
                v.x += rr.x; v.y += rr.y; v.z += rr.z; v.w += rr.w;
            }
            *(float4*)(C + idx) = v;
        }
    }
}

// ---------------- softmax + blend: P = 0.3*softmax(masked S*scale) + M, in place ----------------
__global__ void softmax_blend_kernel(float* __restrict__ S, const float* __restrict__ Mm,
                                     const int* __restrict__ mask) {
    const float SCALE = 0.1767766952966369f;   // 1/sqrt(32)
    long gw = (long)blockIdx.x * 8 + (threadIdx.x >> 5);   // row id in [0, B*H*N)
    int lane = threadIdx.x & 31;
    long b = gw >> 12;          // / (H*N)
    int i = (int)(gw & 511);
    float* row = S + gw * NN;
    const float* mrow = Mm + ((b << 9) + i) * (long)NN;
    const int* mk = mask + (b << 9);

    float s[16];
    int mloc[16];
    #pragma unroll
    for (int t = 0; t < 4; t++) {
        *(float4*)&s[t * 4] = *(const float4*)(row + lane * 16 + t * 4);
        *(int4*)&mloc[t * 4] = *(const int4*)(mk + lane * 16 + t * 4);
    }
    float mx = -INFINITY;
    #pragma unroll
    for (int t = 0; t < 16; t++) if (mloc[t]) mx = fmaxf(mx, s[t]);
    #pragma unroll
    for (int o = 16; o; o >>= 1) mx = fmaxf(mx, __shfl_xor_sync(0xffffffffu, mx, o));

    float e[16];
    float sum = 0.f;
    #pragma unroll
    for (int t = 0; t < 16; t++) {
        e[t] = mloc[t] ? __expf((s[t] - mx) * SCALE) : 0.f;
        sum += e[t];
    }
    #pragma unroll
    for (int o = 16; o; o >>= 1) sum += __shfl_xor_sync(0xffffffffu, sum, o);
    float inv = 0.3f / sum;

    #pragma unroll
    for (int t = 0; t < 4; t++) {
        float4 mv = *(const float4*)(mrow + lane * 16 + t * 4);
        float4 o4;
        o4.x = e[t * 4 + 0] * inv + mv.x;
        o4.y = e[t * 4 + 1] * inv + mv.y;
        o4.z = e[t * 4 + 2] * inv + mv.z;
        o4.w = e[t * 4 + 3] * inv + mv.w;
        *(float4*)(row + lane * 16 + t * 4) = o4;
    }
}

// ---------------- host launch ----------------
extern "C" void kernel_launch(void* const* d_in, const int* in_sizes, int n_in,
                              void* d_out, int out_size) {
    const float* x    = (const float*)d_in[0];
    const int*   mask = (const int*)d_in[1];
    const float* adj  = (const float*)d_in[2];
    const float* dist = (const float*)d_in[3];
    const float* Wq  = (const float*)d_in[5];
    const float* bq  = (const float*)d_in[6];
    const float* Wk  = (const float*)d_in[7];
    const float* bk  = (const float*)d_in[8];
    const float* Wv  = (const float*)d_in[9];
    const float* bv  = (const float*)d_in[10];
    const float* Wo  = (const float*)d_in[11];
    const float* bo  = (const float*)d_in[12];
    const float* Wf1 = (const float*)d_in[13];
    const float* bf1 = (const float*)d_in[14];
    const float* Wf2 = (const float*)d_in[15];
    const float* bf2 = (const float*)d_in[16];
    const float* ln1a = (const float*)d_in[17];
    const float* ln1b = (const float*)d_in[18];
    const float* ln2a = (const float*)d_in[19];
    const float* ln2b = (const float*)d_in[20];
    const float* lnfa = (const float*)d_in[21];
    const float* lnfb = (const float*)d_in[22];

    float *px, *ph, *pqkv, *patt, *ph2, *pM, *pS, *pW, *pb;
    cudaGetSymbolAddress((void**)&px,   g_x);
    cudaGetSymbolAddress((void**)&ph,   g_h);
    cudaGetSymbolAddress((void**)&pqkv, g_qkv);
    cudaGetSymbolAddress((void**)&patt, g_att);
    cudaGetSymbolAddress((void**)&ph2,  g_h2);
    cudaGetSymbolAddress((void**)&pM,   g_M);
    cudaGetSymbolAddress((void**)&pS,   g_S);
    cudaGetSymbolAddress((void**)&pW,   g_Wqkv);
    cudaGetSymbolAddress((void**)&pb,   g_bqkv);

    const int nElem = ROWS_TOTAL * DD;
    copy_kernel<<<(nElem / 4 + 255) / 256, 256>>>((float4*)px, (const float4*)x, nElem / 4);
    pack_qkv_kernel<<<(LL * DD * 3 * DD) / 256, 256>>>(Wq, Wk, Wv, bq, bk, bv, pW, pb);
    precompute_M_kernel<<<dim3(NN, BB), 256>>>(adj, dist, mask, pM);

    const long sS_b = (long)HH * NN * NN;   // S batch strides (z = b*H + h)
    const long sS_h = (long)NN * NN;
    const long sQ_b = (long)NN * 3 * DD;
    const long sQ_h = DK;

    for (int i = 0; i < LL; i++) {
        const float* wo = Wo  + (long)i * DD * DD;
        const float* w1 = Wf1 + (long)i * DD * DD;
        const float* w2 = Wf2 + (long)i * DD * DD;

        // h = LN1(x)
        layernorm_kernel<<<ROWS_TOTAL, 256>>>(px, ph, ln1a + i * DD, ln1b + i * DD);

        // qkv = h @ Wqkv + bqkv   (8192 x 768 x 256)
        gemm_t<128, 128, 16, 16, false><<<dim3(6, 64, 1), 256>>>(
            ph, pW + (long)i * DD * 3 * DD, pb + (long)i * 3 * DD, nullptr, pqkv,
            DD, DD, 3 * DD, 3 * DD, 1, 0, 0, 0, 0, 0, 0, 1);

        // S[z] = Q[z] @ K[z]^T   (512 x 512 x 32, z = b*8+h)
        gemm_t<128, 128, 16, 16, true><<<dim3(4, 4, BB * HH), 256>>>(
            pqkv, pqkv + DD, nullptr, nullptr, pS,
            DK, 3 * DD, 3 * DD, NN, HH, sQ_b, sQ_h, sQ_b, sQ_h, sS_b, sS_h, 0);

        // P = 0.3*softmax(S*scale, masked) + M   (in place)
        softmax_blend_kernel<<<(BB * HH * NN) / 8, 256>>>(pS, pM, mask);

        // att[z cols] = P[z] @ V[z]   (512 x 32 x 512)
        gemm_t<128, 32, 32, 8, false><<<dim3(1, 4, BB * HH), 256>>>(
            pS, pqkv + 2 * DD, nullptr, nullptr, patt,
            NN, NN, 3 * DD, DD, HH, sS_b, sS_h, sQ_b, sQ_h, (long)NN * DD, DK, 0);

        // x = x + att @ Wo + bo
        gemm_t<128, 64, 16, 16, false><<<dim3(4, 64, 1), 256>>>(
            patt, wo, bo + i * DD, px, px,
            DD, DD, DD, DD, 1, 0, 0, 0, 0, 0, 0, 5);

        // h = LN2(x); h2 = lrelu(h@W1+b1); x = x + lrelu(h2@W2+b2)
        layernorm_kernel<<<ROWS_TOTAL, 256>>>(px, ph, ln2a + i * DD, ln2b + i * DD);
        gemm_t<128, 64, 16, 16, false><<<dim3(4, 64, 1), 256>>>(
            ph, w1, bf1 + i * DD, nullptr, ph2,
            DD, DD, DD, DD, 1, 0, 0, 0, 0, 0, 0, 3);
        gemm_t<128, 64, 16, 16, false><<<dim3(4, 64, 1), 256>>>(
            ph2, w2, bf2 + i * DD, px, px,
            DD, DD, DD, DD, 1, 0, 0, 0, 0, 0, 0, 7);
    }

    layernorm_kernel<<<ROWS_TOTAL, 256>>>(px, (float*)d_out, lnfa, lnfb);
}